// round 4
// baseline (speedup 1.0000x reference)
#include <cuda_runtime.h>
#include <math.h>
#include <float.h>
#include <stdint.h>

#define N_NODES 16384
#define D 128
#define BATCH 4
#define WPRIME (0.05f/1.05f)

#define KS 64                    // split-K factor
#define CHUNK (N_NODES / KS)     // 256 nodes per block
#define STAGES 4
#define SROW 136                 // smem row stride (floats), conflict-free fragments

// ---------------- device scratch (no allocations allowed) ----------------
__device__ float g_Rm[BATCH * D * D];
__device__ float g_Rp[(size_t)BATCH * KS * D * D];
__device__ int   g_rowptr[N_NODES + 1];
__device__ float g_partial[BATCH];
// per node 8 rows x 128: [Z0,Z1,Z2,y, LJ0,LJ1,LJ2, gy]
__device__ float g_pan[(size_t)BATCH * N_NODES * 1024];

// ---------------- K1: CSR row pointers (e0 sorted ascending) ----------------
__global__ void rowptr_kernel(const int* __restrict__ e0, int E) {
    int n = blockIdx.x * blockDim.x + threadIdx.x;
    if (n > N_NODES) return;
    int lo = 0, hi = E;
    while (lo < hi) {
        int mid = (lo + hi) >> 1;
        if (e0[mid] < n) lo = mid + 1; else hi = mid;
    }
    g_rowptr[n] = lo;
}

// ---------------- K2a: build per-node panels (gather, MLP-optimized) ----------------
#define MAXDEG 8
__global__ void __launch_bounds__(256)
build_kernel(const float* __restrict__ x, const float* __restrict__ J,
             const int* __restrict__ e1arr) {
    const int b = blockIdx.y;
    const int n = blockIdx.x * 2 + (threadIdx.x >> 7);
    const int c = threadIdx.x & 127;

    const float* xb = x + (size_t)b * N_NODES * 3;
    const float* Jb = J + (size_t)b * N_NODES * 3 * D;

    const float* Jn = Jb + (size_t)(3 * n) * D + c;
    const float Jn0 = Jn[0], Jn1 = Jn[D], Jn2 = Jn[2 * D];
    const float xn0 = xb[3 * n], xn1 = xb[3 * n + 1], xn2 = xb[3 * n + 2];

    const int eBeg = g_rowptr[n], eEnd = g_rowptr[n + 1];
    const int degn = eEnd - eBeg;
    const int dcl = degn < MAXDEG ? degn : MAXDEG;

    // preload edge indices + edge vectors (unrolled register arrays -> high MLP)
    int   ms[MAXDEG];
    float v0a[MAXDEG], v1a[MAXDEG], v2a[MAXDEG];
    float jm0[MAXDEG], jm1[MAXDEG], jm2[MAXDEG];
#pragma unroll
    for (int i = 0; i < MAXDEG; i++) ms[i] = (i < dcl) ? e1arr[eBeg + i] : 0;
#pragma unroll
    for (int i = 0; i < MAXDEG; i++) {
        if (i < dcl) {
            const int m = ms[i];
            v0a[i] = xn0 - xb[3 * m];
            v1a[i] = xn1 - xb[3 * m + 1];
            v2a[i] = xn2 - xb[3 * m + 2];
        }
    }
#pragma unroll
    for (int i = 0; i < MAXDEG; i++) {
        if (i < dcl) {
            const float* Jm = Jb + (size_t)(3 * ms[i]) * D + c;
            jm0[i] = Jm[0]; jm1[i] = Jm[D]; jm2[i] = Jm[2 * D];
        }
    }

    float nb0 = 0.f, nb1 = 0.f, nb2 = 0.f;
    float T0 = 0.f, T1 = 0.f, T2 = 0.f, u = 0.f;
    float deg = 0.f, s0 = 0.f, s1 = 0.f, s2 = 0.f, G = 0.f;
    float c00 = 0.f, c01 = 0.f, c02 = 0.f, c11 = 0.f, c12 = 0.f, c22 = 0.f;

#pragma unroll
    for (int i = 0; i < MAXDEG; i++) {
        if (i < dcl) {
            const float v0 = v0a[i], v1 = v1a[i], v2 = v2a[i];
            const float Jm0 = jm0[i], Jm1 = jm1[i], Jm2 = jm2[i];
            nb0 += Jm0; nb1 += Jm1; nb2 += Jm2;
            T0 += v1 * Jm2 - v2 * Jm1;
            T1 += v2 * Jm0 - v0 * Jm2;
            T2 += v0 * Jm1 - v1 * Jm0;
            u  += v0 * Jm0 + v1 * Jm1 + v2 * Jm2;
            deg += 1.0f; s0 += v0; s1 += v1; s2 += v2;
            const float vv = v0 * v0 + v1 * v1 + v2 * v2;
            G += vv;
            c00 += vv - v0 * v0; c01 -= v0 * v1; c02 -= v0 * v2;
            c11 += vv - v1 * v1; c12 -= v1 * v2; c22 += vv - v2 * v2;
        }
    }
    // safety tail (degree > 8; never taken on this mesh)
    for (int e = eBeg + MAXDEG; e < eEnd; ++e) {
        const int m = e1arr[e];
        const float v0 = xn0 - xb[3 * m];
        const float v1 = xn1 - xb[3 * m + 1];
        const float v2 = xn2 - xb[3 * m + 2];
        const float* Jm = Jb + (size_t)(3 * m) * D + c;
        const float Jm0 = Jm[0], Jm1 = Jm[D], Jm2 = Jm[2 * D];
        nb0 += Jm0; nb1 += Jm1; nb2 += Jm2;
        T0 += v1 * Jm2 - v2 * Jm1;
        T1 += v2 * Jm0 - v0 * Jm2;
        T2 += v0 * Jm1 - v1 * Jm0;
        u  += v0 * Jm0 + v1 * Jm1 + v2 * Jm2;
        deg += 1.0f; s0 += v0; s1 += v1; s2 += v2;
        const float vv = v0 * v0 + v1 * v1 + v2 * v2;
        G += vv;
        c00 += vv - v0 * v0; c01 -= v0 * v1; c02 -= v0 * v2;
        c11 += vv - v1 * v1; c12 -= v1 * v2; c22 += vv - v2 * v2;
    }

    const float LJ0 = 2.0f * (deg * Jn0 - nb0);
    const float LJ1 = 2.0f * (deg * Jn1 - nb1);
    const float LJ2 = 2.0f * (deg * Jn2 - nb2);
    const float B0 = T0 + s2 * Jn1 - s1 * Jn2;
    const float B1 = T1 - s2 * Jn0 + s0 * Jn2;
    const float B2 = T2 + s1 * Jn0 - s0 * Jn1;
    const float y = u - (s0 * Jn0 + s1 * Jn1 + s2 * Jn2);
    const float l00 = sqrtf(c00);
    const float il00 = 1.0f / l00;
    const float l10 = c01 * il00, l20 = c02 * il00;
    const float l11 = sqrtf(c11 - l10 * l10);
    const float il11 = 1.0f / l11;
    const float l21 = (c12 - l20 * l10) * il11;
    const float l22 = sqrtf(c22 - l20 * l20 - l21 * l21);
    const float il22 = 1.0f / l22;
    const float Z0 = B0 * il00;
    const float Z1 = (B1 - l10 * Z0) * il11;
    const float Z2 = (B2 - l20 * Z0 - l21 * Z1) * il22;
    const float Ginv = (G < 1e-6f) ? 0.0f : 1.0f / G;

    float* P = g_pan + ((size_t)b * N_NODES + n) * 1024 + c;
    P[0*128] = Z0;   P[1*128] = Z1;   P[2*128] = Z2;   P[3*128] = y;
    P[4*128] = LJ0;  P[5*128] = LJ1;  P[6*128] = LJ2;
    P[7*128] = -(WPRIME * Ginv) * y;
}

// ---------------- K2b: TF32 tensor-core split-K GEMM ----------------
// smem rows/node: 0:J0 1:J1 2:J2 3:Z0 4:Z1 5:Z2 6:y 7:ZERO 8:LJ0 9:LJ1 10:LJ2 11:gy
// A k-row r -> smem row r.  B k-row r -> {8,9,10, 3-,4-,5-, 11, 7} (- = sign flip)
__device__ __forceinline__ void cp_async16(void* dst_smem, const void* src) {
    uint32_t d = (uint32_t)__cvta_generic_to_shared(dst_smem);
    asm volatile("cp.async.cg.shared.global [%0], [%1], 16;" :: "r"(d), "l"(src));
}
__device__ __forceinline__ void cp_commit() { asm volatile("cp.async.commit_group;"); }
template<int NN> __device__ __forceinline__ void cp_wait() {
    asm volatile("cp.async.wait_group %0;" :: "n"(NN));
}
__device__ __forceinline__ uint32_t tf32c(float f) {
    uint32_t u; asm("cvt.rna.tf32.f32 %0, %1;" : "=r"(u) : "f"(f)); return u;
}
__device__ __forceinline__ void mma_tf32(float* d, uint32_t a0, uint32_t a1,
                                         uint32_t a2, uint32_t a3,
                                         uint32_t b0, uint32_t b1) {
    asm volatile(
        "mma.sync.aligned.m16n8k8.row.col.f32.tf32.tf32.f32 "
        "{%0,%1,%2,%3}, {%4,%5,%6,%7}, {%8,%9}, {%0,%1,%2,%3};"
        : "+f"(d[0]), "+f"(d[1]), "+f"(d[2]), "+f"(d[3])
        : "r"(a0), "r"(a1), "r"(a2), "r"(a3), "r"(b0), "r"(b1));
}

__global__ void __launch_bounds__(256, 2)
gemm_kernel(const float* __restrict__ J) {
    __shared__ __align__(16) float sm[STAGES][12][SROW];

    const int b = blockIdx.y, ks = blockIdx.x;
    const int t = threadIdx.x;
    const int wid = t >> 5, lane = t & 31;
    const int wm = (wid >> 2) * 64;
    const int wn = (wid & 3) * 32;
    const int r0 = lane >> 2, kc = lane & 3;

    const int nodeBase = ks * CHUNK;
    const float* Jb = J + (size_t)b * N_NODES * 3 * D;
    const float* Pb = g_pan + ((size_t)b * N_NODES + nodeBase) * 1024;

    // zero the shared zero-rows (row 7 of each stage); never written again
    for (int idx = t; idx < STAGES * SROW; idx += 256)
        sm[idx / SROW][7][idx % SROW] = 0.0f;

    // B-fragment row LUT + signs (per lane, loop-invariant)
    const int   brow0 = (kc < 3) ? 8 + kc : 3;
    const float bsgn0 = (kc < 3) ? 1.0f : -1.0f;
    const int   brow1 = (kc < 2) ? 4 + kc : ((kc == 2) ? 11 : 7);
    const float bsgn1 = (kc < 2) ? -1.0f : 1.0f;

    float acc[4][4][4];
#pragma unroll
    for (int i = 0; i < 4; i++)
#pragma unroll
        for (int j = 0; j < 4; j++)
#pragma unroll
            for (int r = 0; r < 4; r++) acc[i][j][r] = 0.0f;

    auto issue = [&](int it) {
        const int stg = it & (STAGES - 1);
        const float* psrc = Pb + (size_t)it * 1024;
        // panel: 256 chunks of 16B -> smem rows 3..6, 8..11
        {
            const int prow = t >> 5;
            const int srow = (prow < 4) ? 3 + prow : 4 + prow;
            cp_async16(&sm[stg][srow][(t & 31) * 4], psrc + t * 4);
        }
        // J: 96 chunks of 16B -> smem rows 0..2
        if (t < 96) {
            const float* jsrc = Jb + (size_t)(3 * (nodeBase + it)) * D;
            cp_async16(&sm[stg][t >> 5][(t & 31) * 4], jsrc + t * 4);
        }
    };

    for (int s = 0; s < STAGES - 1; s++) { issue(s); cp_commit(); }

    for (int it = 0; it < CHUNK; ++it) {
        const int stg = it & (STAGES - 1);
        if (it + STAGES - 1 < CHUNK) issue(it + STAGES - 1);
        cp_commit();
        cp_wait<STAGES - 1>();
        __syncthreads();

        const float* S = &sm[stg][0][0];

        uint32_t bb[4][2];
#pragma unroll
        for (int nt = 0; nt < 4; nt++) {
            const int n = wn + nt * 8 + r0;
            bb[nt][0] = tf32c(bsgn0 * S[brow0 * SROW + n]);
            bb[nt][1] = tf32c(bsgn1 * S[brow1 * SROW + n]);
        }
#pragma unroll
        for (int mt = 0; mt < 4; mt++) {
            const int m = wm + mt * 16 + r0;
            const uint32_t a0 = tf32c(S[kc * SROW + m]);
            const uint32_t a1 = tf32c(S[kc * SROW + m + 8]);
            const uint32_t a2 = tf32c(S[(kc + 4) * SROW + m]);
            const uint32_t a3 = tf32c(S[(kc + 4) * SROW + m + 8]);
#pragma unroll
            for (int nt = 0; nt < 4; nt++)
                mma_tf32(acc[mt][nt], a0, a1, a2, a3, bb[nt][0], bb[nt][1]);
        }
        __syncthreads();
    }

    float* out = g_Rp + (((size_t)b * KS + ks) << 14);
#pragma unroll
    for (int mt = 0; mt < 4; mt++) {
        const int m = wm + mt * 16 + r0;
#pragma unroll
        for (int nt = 0; nt < 4; nt++) {
            const int n = wn + nt * 8 + 2 * kc;
            *(float2*)&out[m * 128 + n]       = make_float2(acc[mt][nt][0], acc[mt][nt][1]);
            *(float2*)&out[(m + 8) * 128 + n] = make_float2(acc[mt][nt][2], acc[mt][nt][3]);
        }
    }
}

// ---------------- K2c: reduce split-K partials ----------------
__global__ void reduce_kernel() {
    const int idx = blockIdx.x * 256 + threadIdx.x;
    const int b = idx >> 14;
    const float* p = g_Rp + (((size_t)b * KS) << 14) + (idx & 16383);
    float s = 0.0f;
#pragma unroll 8
    for (int k = 0; k < KS; k++) s += p[(size_t)k << 14];
    g_Rm[idx] = s;
}

// ---------------- 256-thread block reductions ----------------
__device__ __forceinline__ float brs256(float v, float* red) {
#pragma unroll
    for (int off = 16; off > 0; off >>= 1) v += __shfl_down_sync(0xffffffffu, v, off);
    if ((threadIdx.x & 31) == 0) red[threadIdx.x >> 5] = v;
    __syncthreads();
    if (threadIdx.x == 0) {
        float s = 0.f;
#pragma unroll
        for (int i = 0; i < 8; i++) s += red[i];
        red[0] = s;
    }
    __syncthreads();
    const float r = red[0];
    __syncthreads();
    return r;
}
__device__ __forceinline__ float brmin256(float v, float* red) {
#pragma unroll
    for (int off = 16; off > 0; off >>= 1) v = fminf(v, __shfl_down_sync(0xffffffffu, v, off));
    if ((threadIdx.x & 31) == 0) red[threadIdx.x >> 5] = v;
    __syncthreads();
    if (threadIdx.x == 0) {
        float s = red[0];
#pragma unroll
        for (int i = 1; i < 8; i++) s = fminf(s, red[i]);
        red[0] = s;
    }
    __syncthreads();
    const float r = red[0];
    __syncthreads();
    return r;
}
__device__ __forceinline__ float brmax256(float v, float* red) {
#pragma unroll
    for (int off = 16; off > 0; off >>= 1) v = fmaxf(v, __shfl_down_sync(0xffffffffu, v, off));
    if ((threadIdx.x & 31) == 0) red[threadIdx.x >> 5] = v;
    __syncthreads();
    if (threadIdx.x == 0) {
        float s = red[0];
#pragma unroll
        for (int i = 1; i < 8; i++) s = fmaxf(s, red[i]);
        red[0] = s;
    }
    __syncthreads();
    const float r = red[0];
    __syncthreads();
    return r;
}

// ---------------- K3: Householder + Sturm, 256 threads (2 per row) ----------------
#define ASTR 132
#define SMEM_EIG ((128 * ASTR + 4 * 128 + 256 + 32) * 4)

__global__ void eigen_kernel() {
    extern __shared__ float smE[];
    float* A   = smE;                  // 128 x ASTR
    float* uu  = A + 128 * ASTR;       // 128
    float* qq  = uu + 128;             // 128
    float* dd  = qq + 128;             // 128
    float* ee  = dd + 128;             // 128
    float* pp  = ee + 128;             // 256 partial dots
    float* red = pp + 256;             // 32 (also reused as e2 staging? no: separate)

    const int b = blockIdx.x;
    const int t = threadIdx.x;
    const int r = t & 127;
    const int h = t >> 7;              // half selector
    const float* R = g_Rm + (size_t)b * D * D;

    // load + symmetrize (each thread covers 64 rows, column r)
    for (int i = h; i < 128; i += 2)
        A[i * ASTR + r] = 0.5f * (R[i * 128 + r] + R[r * 128 + i]);
    __syncthreads();

    for (int k = 0; k < 126; k++) {
        const float xi = (h == 0 && r > k) ? A[r * ASTR + k] : 0.0f;
        const float sig = brs256(xi * xi, red);
        const float x0 = A[(k + 1) * ASTR + k];
        const float nrm = sqrtf(sig);
        const float alpha = (x0 >= 0.0f) ? -nrm : nrm;
        const float H = sig - alpha * x0;
        if (t == 0) ee[k + 1] = alpha;
        if (h == 0) uu[r] = (r > k) ? (xi - ((r == k + 1) ? alpha : 0.0f)) : 0.0f;
        __syncthreads();
        if (H > 1e-32f) {
            const float invH = 1.0f / H;
            const int j0 = (k + 1) & ~3;
            const int js = (j0 > h * 64) ? j0 : h * 64;
            const int mlen = ((h * 64 + 64) - js) >> 2;    // <=0 -> skip
            float p_part = 0.0f;
            if (r > k && mlen > 0) {
                const float4* Ar4 = (const float4*)(A + r * ASTR + js);
                const float4* U4  = (const float4*)(uu + js);
                float pa0 = 0.f, pa1 = 0.f, pa2 = 0.f, pa3 = 0.f;
#pragma unroll 4
                for (int q = 0; q < mlen; q++) {
                    const float4 a = Ar4[q], u4 = U4[q];
                    if ((q & 3) == 0) pa0 += a.x * u4.x + a.y * u4.y + a.z * u4.z + a.w * u4.w;
                    else if ((q & 3) == 1) pa1 += a.x * u4.x + a.y * u4.y + a.z * u4.z + a.w * u4.w;
                    else if ((q & 3) == 2) pa2 += a.x * u4.x + a.y * u4.y + a.z * u4.z + a.w * u4.w;
                    else pa3 += a.x * u4.x + a.y * u4.y + a.z * u4.z + a.w * u4.w;
                }
                p_part = (pa0 + pa1) + (pa2 + pa3);
            }
            pp[t] = p_part;
            const float ur = uu[r];
            const float Ksum = brs256(ur * p_part * invH, red);   // K = sum_r u_r p_r / H
            const float Kc = Ksum * 0.5f * invH;
            if (h == 0) qq[r] = (pp[r] + pp[r + 128]) * invH - Kc * ur;
            __syncthreads();
            if (r > k && mlen > 0) {
                float4* Ar4 = (float4*)(A + r * ASTR + js);
                const float4* U4 = (const float4*)(uu + js);
                const float4* Q4 = (const float4*)(qq + js);
                const float uif = ur, qif = qq[r];
#pragma unroll 4
                for (int q = 0; q < mlen; q++) {
                    float4 a = Ar4[q];
                    const float4 u4 = U4[q], q4 = Q4[q];
                    a.x -= uif * q4.x + qif * u4.x;
                    a.y -= uif * q4.y + qif * u4.y;
                    a.z -= uif * q4.z + qif * u4.z;
                    a.w -= uif * q4.w + qif * u4.w;
                    Ar4[q] = a;
                }
            }
        }
        __syncthreads();
    }

    if (h == 0) {
        dd[r] = A[r * ASTR + r];
        if (r == 0) ee[0] = 0.0f;
        if (r == 127) ee[127] = A[127 * ASTR + 126];
    }
    __syncthreads();
    // e2 into pp[0..127]
    float* e2 = pp;
    if (h == 0) e2[r] = ee[r] * ee[r];
    float gl_in = FLT_MAX, gu_in = -FLT_MAX;
    if (h == 0) {
        const float rad = fabsf(ee[r]) + ((r < 127) ? fabsf(ee[r + 1]) : 0.0f);
        gl_in = dd[r] - rad;
        gu_in = dd[r] + rad;
    }
    const float gl = brmin256(gl_in, red);
    const float gu = brmax256(gu_in, red);
    __syncthreads();

    const float pivmin = fmaxf(1e-12f * fmaxf(fabsf(gl), fabsf(gu)), 1e-36f);
    float v = 0.0f;
    if (h == 0) {
        float lo = gl, hi = gu;
        for (int iter = 0; iter < 36; ++iter) {
            const float mid = 0.5f * (lo + hi);
            int cnt = 0;
            float q = dd[0] - mid;
            if (q < 0.0f) cnt++;
#pragma unroll 4
            for (int i = 1; i < 128; i++) {
                if (fabsf(q) < pivmin) q = -pivmin;
                q = dd[i] - mid - __fdividef(e2[i], q);
                if (q < 0.0f) cnt++;
            }
            if (cnt > r) hi = mid; else lo = mid;
        }
        const float lam = 0.5f * (lo + hi);
        v = (lam > 0.0f) ? sqrtf(lam) : 0.0f;
    }
    const float s = brs256(v, red);
    if (t == 0) g_partial[b] = s;
}

// ---------------- K4: mean over batch ----------------
__global__ void finalize_kernel(float* out) {
    out[0] = 0.25f * (g_partial[0] + g_partial[1] + g_partial[2] + g_partial[3]);
}

// ---------------- launch ----------------
extern "C" void kernel_launch(void* const* d_in, const int* in_sizes, int n_in,
                              void* d_out, int out_size) {
    const float* x  = (const float*)d_in[0];
    const float* J  = (const float*)d_in[1];
    const int*   ei = (const int*)d_in[2];     // [2, E] int32, e0 sorted
    const int E = in_sizes[2] / 2;
    float* out = (float*)d_out;

    cudaFuncSetAttribute(eigen_kernel,
                         cudaFuncAttributeMaxDynamicSharedMemorySize, SMEM_EIG);

    rowptr_kernel<<<(N_NODES + 1 + 255) / 256, 256>>>(ei, E);

    dim3 gbuild(N_NODES / 2, BATCH);
    build_kernel<<<gbuild, 256>>>(x, J, ei + E);

    dim3 ggemm(KS, BATCH);
    gemm_kernel<<<ggemm, 256>>>(J);
    reduce_kernel<<<BATCH * D * D / 256, 256>>>();

    eigen_kernel<<<BATCH, 256, SMEM_EIG>>>();
    finalize_kernel<<<1, 1>>>(out);
}

// round 5
// speedup vs baseline: 1.2818x; 1.2818x over previous
#include <cuda_runtime.h>
#include <math.h>
#include <stdint.h>

#define N_NODES 16384
#define D 128
#define BATCH 4
#define WPRIME (0.05f/1.05f)

#define KS 64                    // split-K factor
#define CHUNK (N_NODES / KS)     // 256 nodes per block
#define STAGES 4
#define SROW 136                 // smem row stride (floats), conflict-free fragments

// ---------------- device scratch (no allocations allowed) ----------------
__device__ float g_Rm[BATCH * D * D];
__device__ float g_Rp[(size_t)BATCH * KS * D * D];
__device__ int   g_rowptr[N_NODES + 1];
__device__ float g_partial[BATCH];
// per node 8 rows x 128: [Z0,Z1,Z2,y, LJ0,LJ1,LJ2, gy]
__device__ float g_pan[(size_t)BATCH * N_NODES * 1024];

// ---------------- K1: CSR row pointers (e0 sorted ascending) ----------------
__global__ void rowptr_kernel(const int* __restrict__ e0, int E) {
    int n = blockIdx.x * blockDim.x + threadIdx.x;
    if (n > N_NODES) return;
    int lo = 0, hi = E;
    while (lo < hi) {
        int mid = (lo + hi) >> 1;
        if (e0[mid] < n) lo = mid + 1; else hi = mid;
    }
    g_rowptr[n] = lo;
}

// ---------------- K2a: build per-node panels (R3 loop structure, slim output) ----------------
__global__ void __launch_bounds__(256)
build_kernel(const float* __restrict__ x, const float* __restrict__ J,
             const int* __restrict__ e1arr) {
    const int b = blockIdx.y;
    const int n = blockIdx.x * 2 + (threadIdx.x >> 7);
    const int c = threadIdx.x & 127;

    const float* xb = x + (size_t)b * N_NODES * 3;
    const float* Jb = J + (size_t)b * N_NODES * 3 * D;

    const float* Jn = Jb + (size_t)(3 * n) * D + c;
    const float Jn0 = Jn[0], Jn1 = Jn[D], Jn2 = Jn[2 * D];
    const float xn0 = xb[3 * n], xn1 = xb[3 * n + 1], xn2 = xb[3 * n + 2];

    float nb0 = 0.f, nb1 = 0.f, nb2 = 0.f;
    float T0 = 0.f, T1 = 0.f, T2 = 0.f, u = 0.f;
    float deg = 0.f, s0 = 0.f, s1 = 0.f, s2 = 0.f, G = 0.f;
    float c00 = 0.f, c01 = 0.f, c02 = 0.f, c11 = 0.f, c12 = 0.f, c22 = 0.f;

    const int eBeg = g_rowptr[n], eEnd = g_rowptr[n + 1];
#pragma unroll 2
    for (int e = eBeg; e < eEnd; ++e) {
        const int m = e1arr[e];
        const float v0 = xn0 - xb[3 * m];
        const float v1 = xn1 - xb[3 * m + 1];
        const float v2 = xn2 - xb[3 * m + 2];
        const float* Jm = Jb + (size_t)(3 * m) * D + c;
        const float Jm0 = Jm[0], Jm1 = Jm[D], Jm2 = Jm[2 * D];
        nb0 += Jm0; nb1 += Jm1; nb2 += Jm2;
        T0 += v1 * Jm2 - v2 * Jm1;
        T1 += v2 * Jm0 - v0 * Jm2;
        T2 += v0 * Jm1 - v1 * Jm0;
        u  += v0 * Jm0 + v1 * Jm1 + v2 * Jm2;
        deg += 1.0f; s0 += v0; s1 += v1; s2 += v2;
        const float vv = v0 * v0 + v1 * v1 + v2 * v2;
        G += vv;
        c00 += vv - v0 * v0; c01 -= v0 * v1; c02 -= v0 * v2;
        c11 += vv - v1 * v1; c12 -= v1 * v2; c22 += vv - v2 * v2;
    }

    const float LJ0 = 2.0f * (deg * Jn0 - nb0);
    const float LJ1 = 2.0f * (deg * Jn1 - nb1);
    const float LJ2 = 2.0f * (deg * Jn2 - nb2);
    const float B0 = T0 + s2 * Jn1 - s1 * Jn2;
    const float B1 = T1 - s2 * Jn0 + s0 * Jn2;
    const float B2 = T2 + s1 * Jn0 - s0 * Jn1;
    const float y = u - (s0 * Jn0 + s1 * Jn1 + s2 * Jn2);
    // Cholesky C = L L^T, Z = L^{-1} BTJ
    const float l00 = sqrtf(c00);
    const float il00 = 1.0f / l00;
    const float l10 = c01 * il00, l20 = c02 * il00;
    const float l11 = sqrtf(c11 - l10 * l10);
    const float il11 = 1.0f / l11;
    const float l21 = (c12 - l20 * l10) * il11;
    const float l22 = sqrtf(c22 - l20 * l20 - l21 * l21);
    const float il22 = 1.0f / l22;
    const float Z0 = B0 * il00;
    const float Z1 = (B1 - l10 * Z0) * il11;
    const float Z2 = (B2 - l20 * Z0 - l21 * Z1) * il22;
    const float Ginv = (G < 1e-6f) ? 0.0f : 1.0f / G;

    float* P = g_pan + ((size_t)b * N_NODES + n) * 1024 + c;
    P[0*128] = Z0;   P[1*128] = Z1;   P[2*128] = Z2;   P[3*128] = y;
    P[4*128] = LJ0;  P[5*128] = LJ1;  P[6*128] = LJ2;
    P[7*128] = -(WPRIME * Ginv) * y;
}

// ---------------- K2b: TF32 tensor-core split-K GEMM (slim panels) ----------------
// smem rows/node: 0:J0 1:J1 2:J2 3:Z0 4:Z1 5:Z2 6:y 7:ZERO 8:LJ0 9:LJ1 10:LJ2 11:gy
// A k-row r -> smem row r.  B k-row r -> {8,9,10, 3-,4-,5-, 11, 7} (- = sign flip)
__device__ __forceinline__ void cp_async16(void* dst_smem, const void* src) {
    uint32_t d = (uint32_t)__cvta_generic_to_shared(dst_smem);
    asm volatile("cp.async.cg.shared.global [%0], [%1], 16;" :: "r"(d), "l"(src));
}
__device__ __forceinline__ void cp_commit() { asm volatile("cp.async.commit_group;"); }
template<int NN> __device__ __forceinline__ void cp_wait() {
    asm volatile("cp.async.wait_group %0;" :: "n"(NN));
}
__device__ __forceinline__ uint32_t tf32c(float f) {
    uint32_t u; asm("cvt.rna.tf32.f32 %0, %1;" : "=r"(u) : "f"(f)); return u;
}
__device__ __forceinline__ void mma_tf32(float* d, uint32_t a0, uint32_t a1,
                                         uint32_t a2, uint32_t a3,
                                         uint32_t b0, uint32_t b1) {
    asm volatile(
        "mma.sync.aligned.m16n8k8.row.col.f32.tf32.tf32.f32 "
        "{%0,%1,%2,%3}, {%4,%5,%6,%7}, {%8,%9}, {%0,%1,%2,%3};"
        : "+f"(d[0]), "+f"(d[1]), "+f"(d[2]), "+f"(d[3])
        : "r"(a0), "r"(a1), "r"(a2), "r"(a3), "r"(b0), "r"(b1));
}

__global__ void __launch_bounds__(256, 2)
gemm_kernel(const float* __restrict__ J) {
    __shared__ __align__(16) float sm[STAGES][12][SROW];

    const int b = blockIdx.y, ks = blockIdx.x;
    const int t = threadIdx.x;
    const int wid = t >> 5, lane = t & 31;
    const int wm = (wid >> 2) * 64;
    const int wn = (wid & 3) * 32;
    const int r0 = lane >> 2, kc = lane & 3;

    const int nodeBase = ks * CHUNK;
    const float* Jb = J + (size_t)b * N_NODES * 3 * D;
    const float* Pb = g_pan + ((size_t)b * N_NODES + nodeBase) * 1024;

    // zero row 7 of each stage (the k-padding row); never written again
    for (int idx = t; idx < STAGES * SROW; idx += 256)
        sm[idx / SROW][7][idx % SROW] = 0.0f;

    // per-lane B-fragment row LUT + sign (loop-invariant)
    const int   brow0 = (kc < 3) ? 8 + kc : 3;
    const float bsgn0 = (kc < 3) ? 1.0f : -1.0f;
    const int   brow1 = (kc < 2) ? 4 + kc : ((kc == 2) ? 11 : 7);
    const float bsgn1 = (kc < 2) ? -1.0f : 1.0f;

    float acc[4][4][4];
#pragma unroll
    for (int i = 0; i < 4; i++)
#pragma unroll
        for (int j = 0; j < 4; j++)
#pragma unroll
            for (int r = 0; r < 4; r++) acc[i][j][r] = 0.0f;

    auto issue = [&](int it) {
        const int stg = it & (STAGES - 1);
        const float* psrc = Pb + (size_t)it * 1024;
        {   // panel: 256 x 16B -> smem rows 3..6, 8..11
            const int prow = t >> 5;
            const int srow = (prow < 4) ? 3 + prow : 4 + prow;
            cp_async16(&sm[stg][srow][(t & 31) * 4], psrc + t * 4);
        }
        if (t < 96) {   // J: 96 x 16B -> smem rows 0..2
            const float* jsrc = Jb + (size_t)(3 * (nodeBase + it)) * D;
            cp_async16(&sm[stg][t >> 5][(t & 31) * 4], jsrc + t * 4);
        }
    };

    for (int s = 0; s < STAGES - 1; s++) { issue(s); cp_commit(); }

    for (int it = 0; it < CHUNK; ++it) {
        const int stg = it & (STAGES - 1);
        if (it + STAGES - 1 < CHUNK) issue(it + STAGES - 1);
        cp_commit();
        cp_wait<STAGES - 1>();
        __syncthreads();

        const float* S = &sm[stg][0][0];

        uint32_t bb[4][2];
#pragma unroll
        for (int nt = 0; nt < 4; nt++) {
            const int n = wn + nt * 8 + r0;
            bb[nt][0] = tf32c(bsgn0 * S[brow0 * SROW + n]);
            bb[nt][1] = tf32c(bsgn1 * S[brow1 * SROW + n]);
        }
#pragma unroll
        for (int mt = 0; mt < 4; mt++) {
            const int m = wm + mt * 16 + r0;
            const uint32_t a0 = tf32c(S[kc * SROW + m]);
            const uint32_t a1 = tf32c(S[kc * SROW + m + 8]);
            const uint32_t a2 = tf32c(S[(kc + 4) * SROW + m]);
            const uint32_t a3 = tf32c(S[(kc + 4) * SROW + m + 8]);
#pragma unroll
            for (int nt = 0; nt < 4; nt++)
                mma_tf32(acc[mt][nt], a0, a1, a2, a3, bb[nt][0], bb[nt][1]);
        }
        __syncthreads();
    }

    float* out = g_Rp + (((size_t)b * KS + ks) << 14);
#pragma unroll
    for (int mt = 0; mt < 4; mt++) {
        const int m = wm + mt * 16 + r0;
#pragma unroll
        for (int nt = 0; nt < 4; nt++) {
            const int n = wn + nt * 8 + 2 * kc;
            *(float2*)&out[m * 128 + n]       = make_float2(acc[mt][nt][0], acc[mt][nt][1]);
            *(float2*)&out[(m + 8) * 128 + n] = make_float2(acc[mt][nt][2], acc[mt][nt][3]);
        }
    }
}

// ---------------- K2c: reduce split-K partials ----------------
__global__ void reduce_kernel() {
    const int idx = blockIdx.x * 256 + threadIdx.x;
    const int b = idx >> 14;
    const float* p = g_Rp + (((size_t)b * KS) << 14) + (idx & 16383);
    float s = 0.0f;
#pragma unroll 8
    for (int k = 0; k < KS; k++) s += p[(size_t)k << 14];
    g_Rm[idx] = s;
}

// ---------------- block reductions (128 threads) ----------------
__device__ __forceinline__ float blockReduceSum(float v, float* red) {
#pragma unroll
    for (int off = 16; off > 0; off >>= 1) v += __shfl_down_sync(0xffffffffu, v, off);
    if ((threadIdx.x & 31) == 0) red[threadIdx.x >> 5] = v;
    __syncthreads();
    if (threadIdx.x == 0) red[0] = red[0] + red[1] + red[2] + red[3];
    __syncthreads();
    const float r = red[0];
    __syncthreads();
    return r;
}
__device__ __forceinline__ float blockReduceMin(float v, float* red) {
#pragma unroll
    for (int off = 16; off > 0; off >>= 1) v = fminf(v, __shfl_down_sync(0xffffffffu, v, off));
    if ((threadIdx.x & 31) == 0) red[threadIdx.x >> 5] = v;
    __syncthreads();
    if (threadIdx.x == 0) red[0] = fminf(fminf(red[0], red[1]), fminf(red[2], red[3]));
    __syncthreads();
    const float r = red[0];
    __syncthreads();
    return r;
}
__device__ __forceinline__ float blockReduceMax(float v, float* red) {
#pragma unroll
    for (int off = 16; off > 0; off >>= 1) v = fmaxf(v, __shfl_down_sync(0xffffffffu, v, off));
    if ((threadIdx.x & 31) == 0) red[threadIdx.x >> 5] = v;
    __syncthreads();
    if (threadIdx.x == 0) red[0] = fmaxf(fmaxf(red[0], red[1]), fmaxf(red[2], red[3]));
    __syncthreads();
    const float r = red[0];
    __syncthreads();
    return r;
}

// ---------------- K3: Householder + Sturm (R3 version, 128 threads) ----------------
#define ASTR 132
#define SMEM_EIG ((128 * ASTR + 5 * 128 + 32) * 4)

__global__ void eigen_kernel() {
    extern __shared__ float smE[];
    float* A   = smE;
    float* uu  = A + 128 * ASTR;
    float* qq  = uu + 128;
    float* dd  = qq + 128;
    float* ee  = dd + 128;
    float* e2  = ee + 128;
    float* red = e2 + 128;

    const int b = blockIdx.x;
    const int t = threadIdx.x;
    const float* R = g_Rm + (size_t)b * D * D;

#pragma unroll 4
    for (int i = 0; i < 128; i++)
        A[i * ASTR + t] = 0.5f * (R[i * 128 + t] + R[t * 128 + i]);
    __syncthreads();

    for (int k = 0; k < 126; k++) {
        const float xi = (t > k) ? A[t * ASTR + k] : 0.0f;
        const float sig = blockReduceSum(xi * xi, red);
        const float x0 = A[(k + 1) * ASTR + k];
        const float nrm = sqrtf(sig);
        const float alpha = (x0 >= 0.0f) ? -nrm : nrm;
        const float H = sig - alpha * x0;
        if (t == 0) ee[k + 1] = alpha;
        const float ui = (t > k) ? (xi - ((t == k + 1) ? alpha : 0.0f)) : 0.0f;
        uu[t] = ui;
        __syncthreads();
        if (H > 1e-32f) {
            const float invH = 1.0f / H;
            const int j0 = (k + 1) & ~3;        // u,q are exactly 0 for j<=k
            const int m = (128 - j0) >> 2;
            float p = 0.0f;
            if (t > k) {
                const float4* Ar4 = (const float4*)(A + t * ASTR + j0);
                const float4* U4  = (const float4*)(uu + j0);
                float pa[4] = {0.f, 0.f, 0.f, 0.f};
#pragma unroll 4
                for (int q = 0; q < m; q++) {
                    const float4 a = Ar4[q], u4 = U4[q];
                    pa[q & 3] += a.x * u4.x + a.y * u4.y + a.z * u4.z + a.w * u4.w;
                }
                p = ((pa[0] + pa[1]) + (pa[2] + pa[3])) * invH;
            }
            const float Ks = blockReduceSum(ui * p, red);
            const float Kc = Ks * 0.5f * invH;
            qq[t] = p - Kc * ui;
            __syncthreads();
            if (t > k) {
                float4* Ar4 = (float4*)(A + t * ASTR + j0);
                const float4* U4 = (const float4*)(uu + j0);
                const float4* Q4 = (const float4*)(qq + j0);
                const float uif = ui, qif = qq[t];
#pragma unroll 4
                for (int q = 0; q < m; q++) {
                    float4 a = Ar4[q];
                    const float4 u4 = U4[q], q4 = Q4[q];
                    a.x -= uif * q4.x + qif * u4.x;
                    a.y -= uif * q4.y + qif * u4.y;
                    a.z -= uif * q4.z + qif * u4.z;
                    a.w -= uif * q4.w + qif * u4.w;
                    Ar4[q] = a;
                }
            }
        }
        __syncthreads();
    }

    dd[t] = A[t * ASTR + t];
    if (t == 0) { ee[0] = 0.0f; ee[127] = A[127 * ASTR + 126]; }
    __syncthreads();
    e2[t] = ee[t] * ee[t];
    const float rad = fabsf(ee[t]) + ((t < 127) ? fabsf(ee[t + 1]) : 0.0f);
    const float gl = blockReduceMin(dd[t] - rad, red);
    const float gu = blockReduceMax(dd[t] + rad, red);
    __syncthreads();

    const float pivmin = fmaxf(1e-12f * fmaxf(fabsf(gl), fabsf(gu)), 1e-36f);
    float lo = gl, hi = gu;
    for (int iter = 0; iter < 36; ++iter) {
        const float mid = 0.5f * (lo + hi);
        int cnt = 0;
        float q = dd[0] - mid;
        if (q < 0.0f) cnt++;
#pragma unroll 4
        for (int i = 1; i < 128; i++) {
            if (fabsf(q) < pivmin) q = -pivmin;
            q = dd[i] - mid - __fdividef(e2[i], q);
            if (q < 0.0f) cnt++;
        }
        if (cnt > t) hi = mid; else lo = mid;
    }
    const float lam = 0.5f * (lo + hi);
    const float v = (lam > 0.0f) ? sqrtf(lam) : 0.0f;
    const float s = blockReduceSum(v, red);
    if (t == 0) g_partial[b] = s;
}

// ---------------- K4: mean over batch ----------------
__global__ void finalize_kernel(float* out) {
    out[0] = 0.25f * (g_partial[0] + g_partial[1] + g_partial[2] + g_partial[3]);
}

// ---------------- launch ----------------
extern "C" void kernel_launch(void* const* d_in, const int* in_sizes, int n_in,
                              void* d_out, int out_size) {
    const float* x  = (const float*)d_in[0];
    const float* J  = (const float*)d_in[1];
    const int*   ei = (const int*)d_in[2];     // [2, E] int32, e0 sorted
    const int E = in_sizes[2] / 2;
    float* out = (float*)d_out;

    cudaFuncSetAttribute(eigen_kernel,
                         cudaFuncAttributeMaxDynamicSharedMemorySize, SMEM_EIG);

    rowptr_kernel<<<(N_NODES + 1 + 255) / 256, 256>>>(ei, E);

    dim3 gbuild(N_NODES / 2, BATCH);
    build_kernel<<<gbuild, 256>>>(x, J, ei + E);

    dim3 ggemm(KS, BATCH);
    gemm_kernel<<<ggemm, 256>>>(J);
    reduce_kernel<<<BATCH * D * D / 256, 256>>>();

    eigen_kernel<<<BATCH, 128, SMEM_EIG>>>();
    finalize_kernel<<<1, 1>>>(out);
}